// round 11
// baseline (speedup 1.0000x reference)
#include <cuda_runtime.h>
#include <cuda.h>
#include <cstdint>

// BicycleModel: B=65536 vehicles, 256 steps, 4 output planes [B,256] f32.
// R11 = R10's full double-buffered TMA pipeline compressed to 16KB smem:
//  - ctrl: 16t SW64 tiles, 2 bufs, TMA 2D loads, prefetch distance 2 (as R10)
//  - state: 8t SW32 tiles (32v x 8t x 4 planes = 4KB), 2 bufs, one 3D TMA
//    store {8,32,4} per HALF-chunk, recycled via wait_group.read 1
//  - 16KB/block -> ~14 blocks/SM -> single resident wave (2048 jobs)
//  - runtime swizzle phase for BOTH SW64 (ctrl) and SW32 (state)

constexpr int BV  = 65536;
constexpr int NS  = 256;
constexpr int BLK = 32;
constexpr int NCH = 16;            // control chunks of 16 timesteps
constexpr int CT4 = 128;           // float4 per 32x16 f32 ctrl tile (2KB)
constexpr int SB4 = 256;           // float4 per state buffer (4 planes x 64)

constexpr float DT        = 0.05f;
constexpr float MAX_STEER = 0.52359877559829887f;
constexpr float MAX_SPEED = 100.0f;
constexpr float INV_WB    = 1.0f / 2.7f;

__device__ __forceinline__ uint32_t s2u(const void* p) {
    uint32_t a;
    asm("{ .reg .u64 t; cvta.to.shared.u64 t, %1; cvt.u32.u64 %0, t; }"
        : "=r"(a) : "l"(p));
    return a;
}

__global__ __launch_bounds__(BLK)
void bicycle_kernel(const __grid_constant__ CUtensorMap ta,   // acc  [B,256]
                    const __grid_constant__ CUtensorMap ts,   // steer[B,256]
                    const __grid_constant__ CUtensorMap to,   // out  [4,B,256]
                    const float* __restrict__ sx,
                    const float* __restrict__ sy,
                    const float* __restrict__ syaw,
                    const float* __restrict__ ssp)
{
    // Pool (16KB): cA[2][128] | cS[2][128] | sT[2][4][64]
    // ctrl bufs at 2KB multiples (uniform SW64 phase);
    // state bufs/planes at 1KB multiples (uniform SW32 phase).
    __shared__ alignas(1024) float4 pool[1024];
    __shared__ alignas(8) unsigned long long mb[2];

    float4* cA = pool;                 // [2][128] accel tiles
    float4* cS = pool + 2 * CT4;       // [2][128] steer tiles
    float4* sT = pool + 4 * CT4;       // [2][4][64] state planes

    const int lane = threadIdx.x;
    const int vb   = blockIdx.x * BLK;
    const int b    = vb + lane;

    float x   = sx[b];
    float y   = sy[b];
    float yaw = syaw[b];
    float sp  = ssp[b];

    const uint32_t mb0 = s2u(&mb[0]);
    const uint32_t cAu = s2u(cA);
    const uint32_t cSu = s2u(cS);
    const uint32_t sTu = s2u(sT);

    // SW64 (ctrl, 64B rows): f4 col = q ^ (((base>>7) + (v>>1)) & 3)
    const int sw64 = (int)(((cAu >> 7) + (lane >> 1)) & 3);
    // SW32 (state, 32B rows): f4 col = q ^ (((base>>7) + (v>>2)) & 1)
    const int sw32 = (int)(((sTu >> 7) + (lane >> 2)) & 1);

    if (lane == 0) {
        asm volatile("mbarrier.init.shared.b64 [%0], 1;" :: "r"(mb0) : "memory");
        asm volatile("mbarrier.init.shared.b64 [%0], 1;" :: "r"(mb0 + 8) : "memory");
        asm volatile("fence.proxy.async.shared::cta;" ::: "memory");
    }
    __syncwarp();

#define ISSUE_LOAD(cc) do {                                                   \
        uint32_t mbar = mb0 + ((cc) & 1) * 8;                                 \
        uint32_t da = cAu + ((cc) & 1) * (CT4 * 16);                          \
        uint32_t ds = cSu + ((cc) & 1) * (CT4 * 16);                          \
        asm volatile("mbarrier.arrive.expect_tx.shared.b64 _, [%0], %1;"      \
                     :: "r"(mbar), "r"(4096u) : "memory");                    \
        asm volatile("cp.async.bulk.tensor.2d.shared::cta.global.tile"        \
                     ".mbarrier::complete_tx::bytes [%0], [%1, {%2, %3}], [%4];" \
                     :: "r"(da), "l"(&ta), "r"((cc) * 16), "r"(vb), "r"(mbar) \
                     : "memory");                                             \
        asm volatile("cp.async.bulk.tensor.2d.shared::cta.global.tile"        \
                     ".mbarrier::complete_tx::bytes [%0], [%1, {%2, %3}], [%4];" \
                     :: "r"(ds), "l"(&ts), "r"((cc) * 16), "r"(vb), "r"(mbar) \
                     : "memory");                                             \
    } while (0)

    if (lane == 0) { ISSUE_LOAD(0); ISSUE_LOAD(1); }

#define STEP(A, ST) do {                                                     \
        float fr   = fmaf(0.01f * sp, sp, 0.1f * sp);                        \
        float spn  = fminf(fmaxf(fmaf(DT, (A) - fr, sp), 0.0f), MAX_SPEED);  \
        float sc   = fminf(fmaxf((ST), -MAX_STEER), MAX_STEER);              \
        float angv = sp * __tanf(sc) * INV_WB;                               \
        float sn, cc2;                                                       \
        __sincosf(yaw, &sn, &cc2);                                           \
        x   = fmaf(sp * cc2, DT, x);                                         \
        y   = fmaf(sp * sn, DT, y);                                          \
        yaw = fmaf(angv, DT, yaw);                                           \
        sp  = spn;                                                           \
    } while (0)

    for (int c = 0; c < NCH; ++c) {
        const int buf = c & 1;
        const int ph  = (c >> 1) & 1;

        // Wait for this chunk's control tiles (acquire).
        {
            uint32_t mbar = mb0 + buf * 8;
            uint32_t done;
            asm volatile("{\n\t.reg .pred p;\n\t"
                         "mbarrier.try_wait.parity.acquire.cta.shared::cta.b64 p, [%1], %2;\n\t"
                         "selp.b32 %0, 1, 0, p;\n\t}"
                         : "=r"(done) : "r"(mbar), "r"(ph) : "memory");
            if (!done) {
                asm volatile("{\n\t.reg .pred P1;\n\t"
                             "W%=:\n\t"
                             "mbarrier.try_wait.parity.acquire.cta.shared::cta.b64 P1, [%0], %1, 0x989680;\n\t"
                             "@P1 bra.uni D%=;\n\t"
                             "bra.uni W%=;\n\t"
                             "D%=:\n\t}"
                             :: "r"(mbar), "r"(ph) : "memory");
            }
        }

        const float4* A4p = cA + buf * CT4;
        const float4* S4p = cS + buf * CT4;

        // Two half-chunks of 8 steps; each gets its own state buffer + store.
#pragma unroll
        for (int h = 0; h < 2; ++h) {
            const int s    = 2 * c + h;          // global store-phase index
            const int sbuf = s & 1;

            // Recycle state buffer: store s-2 (same buffer) must be done
            // reading smem; tolerate 1 outstanding group (s-1) -> overlap.
            if (s >= 2) {
                if (lane == 0)
                    asm volatile("cp.async.bulk.wait_group.read 1;" ::: "memory");
                __syncwarp();
            }

            float4* P = sT + sbuf * SB4;         // 4 planes x 64 f4

#pragma unroll
            for (int j = 0; j < 2; ++j) {        // two f4 columns per half
                const int q  = 2 * h + j;        // ctrl f4 column (0..3)
                const int ci = lane * 4 + (q ^ sw64);
                float4 A4 = A4p[ci];
                float4 S4 = S4p[ci];
                float4 X, Y, W, S;
                X.x = x; Y.x = y; W.x = yaw; S.x = sp;  STEP(A4.x, S4.x);
                X.y = x; Y.y = y; W.y = yaw; S.y = sp;  STEP(A4.y, S4.y);
                X.z = x; Y.z = y; W.z = yaw; S.z = sp;  STEP(A4.z, S4.z);
                X.w = x; Y.w = y; W.w = yaw; S.w = sp;  STEP(A4.w, S4.w);
                const int si = lane * 2 + (j ^ sw32);
                P[si]       = X;                 // plane 0: x
                P[64 + si]  = Y;                 // plane 1: y
                P[128 + si] = W;                 // plane 2: yaw
                P[192 + si] = S;                 // plane 3: speed
            }
            __syncwarp();

            if (lane == 0) {
                asm volatile("fence.proxy.async.shared::cta;" ::: "memory");
                uint32_t src = sTu + sbuf * (SB4 * 16);
                asm volatile("cp.async.bulk.tensor.3d.global.shared::cta.tile.bulk_group"
                             " [%0, {%1, %2, %3}], [%4];"
                             :: "l"(&to), "r"(c * 16 + h * 8), "r"(vb), "r"(0),
                                "r"(src)
                             : "memory");
                asm volatile("cp.async.bulk.commit_group;" ::: "memory");
                if (h == 1 && c + 2 < NCH) ISSUE_LOAD(c + 2);
            }
            __syncwarp();
        }
    }

    if (lane == 0)
        asm volatile("cp.async.bulk.wait_group 0;" ::: "memory");
#undef STEP
#undef ISSUE_LOAD
}

// ---------------- host ----------------

typedef CUresult (*EncodeFn)(CUtensorMap*, CUtensorMapDataType, cuuint32_t, void*,
                             const cuuint64_t*, const cuuint64_t*,
                             const cuuint32_t*, const cuuint32_t*,
                             CUtensorMapInterleave, CUtensorMapSwizzle,
                             CUtensorMapL2promotion, CUtensorMapFloatOOBfill);

extern "C" void kernel_launch(void* const* d_in, const int* in_sizes, int n_in,
                              void* d_out, int out_size)
{
    (void)in_sizes; (void)n_in; (void)out_size;

    void* fptr = nullptr;
    cudaDriverEntryPointQueryResult qr;
    cudaGetDriverEntryPointByVersion("cuTensorMapEncodeTiled", &fptr, 12000,
                                     cudaEnableDefault, &qr);
    EncodeFn encode = (EncodeFn)fptr;

    CUtensorMap ta, ts, to;

    // controls: [B, 256] f32, tile 16x32, SW64 (64B rows)
    {
        cuuint64_t dims[2]    = {NS, BV};
        cuuint64_t strides[1] = {NS * 4};
        cuuint32_t box[2]     = {16, 32};
        cuuint32_t es[2]      = {1, 1};
        encode(&ta, CU_TENSOR_MAP_DATA_TYPE_FLOAT32, 2, d_in[4], dims, strides,
               box, es, CU_TENSOR_MAP_INTERLEAVE_NONE, CU_TENSOR_MAP_SWIZZLE_64B,
               CU_TENSOR_MAP_L2_PROMOTION_L2_128B, CU_TENSOR_MAP_FLOAT_OOB_FILL_NONE);
        encode(&ts, CU_TENSOR_MAP_DATA_TYPE_FLOAT32, 2, d_in[5], dims, strides,
               box, es, CU_TENSOR_MAP_INTERLEAVE_NONE, CU_TENSOR_MAP_SWIZZLE_64B,
               CU_TENSOR_MAP_L2_PROMOTION_L2_128B, CU_TENSOR_MAP_FLOAT_OOB_FILL_NONE);
    }
    // output: [4, B, 256] f32, tile 8x32x4, SW32 (32B rows)
    {
        cuuint64_t dims[3]    = {NS, BV, 4};
        cuuint64_t strides[2] = {NS * 4, (cuuint64_t)BV * NS * 4};
        cuuint32_t box[3]     = {8, 32, 4};
        cuuint32_t es[3]      = {1, 1, 1};
        encode(&to, CU_TENSOR_MAP_DATA_TYPE_FLOAT32, 3, d_out, dims, strides,
               box, es, CU_TENSOR_MAP_INTERLEAVE_NONE, CU_TENSOR_MAP_SWIZZLE_32B,
               CU_TENSOR_MAP_L2_PROMOTION_L2_128B, CU_TENSOR_MAP_FLOAT_OOB_FILL_NONE);
    }

    bicycle_kernel<<<BV / BLK, BLK>>>(
        ta, ts, to,
        (const float*)d_in[0], (const float*)d_in[1],
        (const float*)d_in[2], (const float*)d_in[3]);
}

// round 12
// speedup vs baseline: 1.0256x; 1.0256x over previous
#include <cuda_runtime.h>
#include <cuda.h>
#include <cstdint>

// BicycleModel: B=65536 vehicles, 256 steps, 4 output planes [B,256] f32.
// R12 = R10's pipeline (TC=16, SW64 tiles, double-buffered ctrl loads +
// state stores) with TWO sequential jobs per block:
//  - grid 1024 one-warp blocks, 24KB smem, 9 blocks/SM capacity
//  - 1024 <= 1332 slots -> SINGLE wave, ~1% imbalance (R10 ran 1.54 ragged
//    waves; its tail was the whole gap to ~80% DRAM)
//  - the 32-chunk pipeline runs continuously across the job boundary
//    (prefetch distance 2 spans it; mbarrier phases just keep alternating)

constexpr int BV  = 65536;
constexpr int NS  = 256;
constexpr int BLK = 32;
constexpr int NCH = 32;            // 2 jobs x 16 chunks of 16 timesteps
constexpr int CT4 = 128;           // float4 per 32x16 f32 tile (2KB)

constexpr float DT        = 0.05f;
constexpr float MAX_STEER = 0.52359877559829887f;
constexpr float MAX_SPEED = 100.0f;
constexpr float INV_WB    = 1.0f / 2.7f;

__device__ __forceinline__ uint32_t s2u(const void* p) {
    uint32_t a;
    asm("{ .reg .u64 t; cvta.to.shared.u64 t, %1; cvt.u32.u64 %0, t; }"
        : "=r"(a) : "l"(p));
    return a;
}

__global__ __launch_bounds__(BLK)
void bicycle_kernel(const __grid_constant__ CUtensorMap ta,   // acc  [B,256]
                    const __grid_constant__ CUtensorMap ts,   // steer[B,256]
                    const __grid_constant__ CUtensorMap to,   // out  [4,B,256]
                    const float* __restrict__ sx,
                    const float* __restrict__ sy,
                    const float* __restrict__ syaw,
                    const float* __restrict__ ssp)
{
    // Pool: cA[2][128] | cS[2][128] | sT[2][4][128]  = 24KB.
    // All sub-buffers at 2KB multiples -> uniform SW64 phase.
    __shared__ alignas(1024) float4 pool[1536];
    __shared__ alignas(8) unsigned long long mb[2];

    float4* cA = pool;                 // [2][128] accel tiles
    float4* cS = pool + 2 * CT4;       // [2][128] steer tiles
    float4* sT = pool + 4 * CT4;       // [2][4][128] state planes

    const int lane = threadIdx.x;
    const int vb0  = blockIdx.x * 64;            // job 0 base; job 1 = vb0+32
    const int b0   = vb0 + lane;

    // Preload BOTH jobs' initial states (job switch costs nothing later).
    float x  = sx[b0],      y  = sy[b0];
    float yaw = syaw[b0],   sp = ssp[b0];
    const float x1 = sx[b0 + 32],   y1 = sy[b0 + 32];
    const float w1 = syaw[b0 + 32], s1 = ssp[b0 + 32];

    const uint32_t mb0u = s2u(&mb[0]);
    const uint32_t cAu  = s2u(cA);
    const uint32_t cSu  = s2u(cS);
    const uint32_t sTu  = s2u(sT);

    // SW64 swizzle: f4 column = q ^ (((base>>7) + (v>>1)) & 3).
    const int sw = (int)(((cAu >> 7) + (lane >> 1)) & 3);

    if (lane == 0) {
        asm volatile("mbarrier.init.shared.b64 [%0], 1;" :: "r"(mb0u) : "memory");
        asm volatile("mbarrier.init.shared.b64 [%0], 1;" :: "r"(mb0u + 8) : "memory");
        asm volatile("fence.proxy.async.shared::cta;" ::: "memory");
    }
    __syncwarp();

    // Global chunk index g in [0,32): job = g>>4, time coord = (g&15)*16,
    // vehicle base = vb0 + (g>>4)*32.
#define ISSUE_LOAD(gg) do {                                                   \
        uint32_t mbar = mb0u + ((gg) & 1) * 8;                                \
        uint32_t da = cAu + ((gg) & 1) * (CT4 * 16);                          \
        uint32_t ds = cSu + ((gg) & 1) * (CT4 * 16);                          \
        int vcoord = vb0 + (((gg) >> 4) << 5);                                \
        int tcoord = ((gg) & 15) * 16;                                        \
        asm volatile("mbarrier.arrive.expect_tx.shared.b64 _, [%0], %1;"      \
                     :: "r"(mbar), "r"(4096u) : "memory");                    \
        asm volatile("cp.async.bulk.tensor.2d.shared::cta.global.tile"        \
                     ".mbarrier::complete_tx::bytes [%0], [%1, {%2, %3}], [%4];" \
                     :: "r"(da), "l"(&ta), "r"(tcoord), "r"(vcoord), "r"(mbar) \
                     : "memory");                                             \
        asm volatile("cp.async.bulk.tensor.2d.shared::cta.global.tile"        \
                     ".mbarrier::complete_tx::bytes [%0], [%1, {%2, %3}], [%4];" \
                     :: "r"(ds), "l"(&ts), "r"(tcoord), "r"(vcoord), "r"(mbar) \
                     : "memory");                                             \
    } while (0)

    if (lane == 0) { ISSUE_LOAD(0); ISSUE_LOAD(1); }

#define STEP(A, ST) do {                                                     \
        float fr   = fmaf(0.01f * sp, sp, 0.1f * sp);                        \
        float spn  = fminf(fmaxf(fmaf(DT, (A) - fr, sp), 0.0f), MAX_SPEED);  \
        float sc   = fminf(fmaxf((ST), -MAX_STEER), MAX_STEER);              \
        float angv = sp * __tanf(sc) * INV_WB;                               \
        float sn, cc2;                                                       \
        __sincosf(yaw, &sn, &cc2);                                           \
        x   = fmaf(sp * cc2, DT, x);                                         \
        y   = fmaf(sp * sn, DT, y);                                          \
        yaw = fmaf(angv, DT, yaw);                                           \
        sp  = spn;                                                           \
    } while (0)

    for (int g = 0; g < NCH; ++g) {
        const int buf = g & 1;
        const int ph  = (g >> 1) & 1;

        // Job switch: reset state registers for the second vehicle group.
        if (g == 16) { x = x1; y = y1; yaw = w1; sp = s1; }

        // Wait for this chunk's control tiles (acquire).
        {
            uint32_t mbar = mb0u + buf * 8;
            uint32_t done;
            asm volatile("{\n\t.reg .pred p;\n\t"
                         "mbarrier.try_wait.parity.acquire.cta.shared::cta.b64 p, [%1], %2;\n\t"
                         "selp.b32 %0, 1, 0, p;\n\t}"
                         : "=r"(done) : "r"(mbar), "r"(ph) : "memory");
            if (!done) {
                asm volatile("{\n\t.reg .pred P1;\n\t"
                             "W%=:\n\t"
                             "mbarrier.try_wait.parity.acquire.cta.shared::cta.b64 P1, [%0], %1, 0x989680;\n\t"
                             "@P1 bra.uni D%=;\n\t"
                             "bra.uni W%=;\n\t"
                             "D%=:\n\t}"
                             :: "r"(mbar), "r"(ph) : "memory");
            }
        }

        // State buffer reuse: chunk g-2's TMA store (same buffer) must be
        // done reading smem; tolerate one outstanding group -> overlap.
        if (g >= 2) {
            if (lane == 0)
                asm volatile("cp.async.bulk.wait_group.read 1;" ::: "memory");
            __syncwarp();
        }

        const float4* A4p = cA + buf * CT4;
        const float4* S4p = cS + buf * CT4;
        float4* P = sT + buf * (4 * CT4);

#pragma unroll
        for (int q = 0; q < 4; ++q) {
            const int si = lane * 4 + (q ^ sw);
            float4 A4 = A4p[si];
            float4 S4 = S4p[si];
            float4 X, Y, W, S;
            X.x = x; Y.x = y; W.x = yaw; S.x = sp;  STEP(A4.x, S4.x);
            X.y = x; Y.y = y; W.y = yaw; S.y = sp;  STEP(A4.y, S4.y);
            X.z = x; Y.z = y; W.z = yaw; S.z = sp;  STEP(A4.z, S4.z);
            X.w = x; Y.w = y; W.w = yaw; S.w = sp;  STEP(A4.w, S4.w);
            P[si]       = X;            // plane 0: x
            P[128 + si] = Y;            // plane 1: y
            P[256 + si] = W;            // plane 2: yaw
            P[384 + si] = S;            // plane 3: speed
        }
        __syncwarp();

        // One 3D TMA store covers all 4 planes; then prefetch chunk g+2.
        if (lane == 0) {
            asm volatile("fence.proxy.async.shared::cta;" ::: "memory");
            uint32_t src = sTu + buf * (4 * CT4 * 16);
            int vcoord = vb0 + ((g >> 4) << 5);
            int tcoord = (g & 15) * 16;
            asm volatile("cp.async.bulk.tensor.3d.global.shared::cta.tile.bulk_group"
                         " [%0, {%1, %2, %3}], [%4];"
                         :: "l"(&to), "r"(tcoord), "r"(vcoord), "r"(0), "r"(src)
                         : "memory");
            asm volatile("cp.async.bulk.commit_group;" ::: "memory");
            if (g + 2 < NCH) ISSUE_LOAD(g + 2);
        }
        __syncwarp();
    }

    if (lane == 0)
        asm volatile("cp.async.bulk.wait_group 0;" ::: "memory");
#undef STEP
#undef ISSUE_LOAD
}

// ---------------- host ----------------

typedef CUresult (*EncodeFn)(CUtensorMap*, CUtensorMapDataType, cuuint32_t, void*,
                             const cuuint64_t*, const cuuint64_t*,
                             const cuuint32_t*, const cuuint32_t*,
                             CUtensorMapInterleave, CUtensorMapSwizzle,
                             CUtensorMapL2promotion, CUtensorMapFloatOOBfill);

extern "C" void kernel_launch(void* const* d_in, const int* in_sizes, int n_in,
                              void* d_out, int out_size)
{
    (void)in_sizes; (void)n_in; (void)out_size;

    void* fptr = nullptr;
    cudaDriverEntryPointQueryResult qr;
    cudaGetDriverEntryPointByVersion("cuTensorMapEncodeTiled", &fptr, 12000,
                                     cudaEnableDefault, &qr);
    EncodeFn encode = (EncodeFn)fptr;

    CUtensorMap ta, ts, to;

    // controls: [B, 256] f32, tile 16x32, SW64 (64B rows)
    {
        cuuint64_t dims[2]    = {NS, BV};
        cuuint64_t strides[1] = {NS * 4};
        cuuint32_t box[2]     = {16, 32};
        cuuint32_t es[2]      = {1, 1};
        encode(&ta, CU_TENSOR_MAP_DATA_TYPE_FLOAT32, 2, d_in[4], dims, strides,
               box, es, CU_TENSOR_MAP_INTERLEAVE_NONE, CU_TENSOR_MAP_SWIZZLE_64B,
               CU_TENSOR_MAP_L2_PROMOTION_L2_128B, CU_TENSOR_MAP_FLOAT_OOB_FILL_NONE);
        encode(&ts, CU_TENSOR_MAP_DATA_TYPE_FLOAT32, 2, d_in[5], dims, strides,
               box, es, CU_TENSOR_MAP_INTERLEAVE_NONE, CU_TENSOR_MAP_SWIZZLE_64B,
               CU_TENSOR_MAP_L2_PROMOTION_L2_128B, CU_TENSOR_MAP_FLOAT_OOB_FILL_NONE);
    }
    // output: [4, B, 256] f32, tile 16x32x4, SW64
    {
        cuuint64_t dims[3]    = {NS, BV, 4};
        cuuint64_t strides[2] = {NS * 4, (cuuint64_t)BV * NS * 4};
        cuuint32_t box[3]     = {16, 32, 4};
        cuuint32_t es[3]      = {1, 1, 1};
        encode(&to, CU_TENSOR_MAP_DATA_TYPE_FLOAT32, 3, d_out, dims, strides,
               box, es, CU_TENSOR_MAP_INTERLEAVE_NONE, CU_TENSOR_MAP_SWIZZLE_64B,
               CU_TENSOR_MAP_L2_PROMOTION_L2_128B, CU_TENSOR_MAP_FLOAT_OOB_FILL_NONE);
    }

    bicycle_kernel<<<BV / 64, BLK>>>(
        ta, ts, to,
        (const float*)d_in[0], (const float*)d_in[1],
        (const float*)d_in[2], (const float*)d_in[3]);
}

// round 13
// speedup vs baseline: 1.0478x; 1.0217x over previous
#include <cuda_runtime.h>
#include <cuda.h>
#include <cstdint>

// BicycleModel: B=65536 vehicles, 256 steps, 4 output planes [B,256] f32.
// R13 = R12 (single-wave, 2 jobs/block, TC=16 SW64 TMA pipeline) +
//  - TRIPLE-buffered control loads: load g+2 issued at TOP of chunk g
//    (one full compute+store phase earlier than R12's end-of-chunk issue),
//    keeping 2 chunks of loads continuously in flight per warp
//  - L2 promotion 256B on all tensormaps
//  - state: 2 x 8KB, one 3D TMA store {16,32,4}/chunk, wait_group.read 1
//  - smem 28KB -> 8 blocks/SM capacity, 7 resident (1024 blocks, 1 wave)

constexpr int BV  = 65536;
constexpr int NS  = 256;
constexpr int BLK = 32;
constexpr int NCH = 32;            // 2 jobs x 16 chunks of 16 timesteps
constexpr int CT4 = 128;           // float4 per 32x16 f32 tile (2KB)

constexpr float DT        = 0.05f;
constexpr float MAX_STEER = 0.52359877559829887f;
constexpr float MAX_SPEED = 100.0f;
constexpr float INV_WB    = 1.0f / 2.7f;

__device__ __forceinline__ uint32_t s2u(const void* p) {
    uint32_t a;
    asm("{ .reg .u64 t; cvta.to.shared.u64 t, %1; cvt.u32.u64 %0, t; }"
        : "=r"(a) : "l"(p));
    return a;
}

__global__ __launch_bounds__(BLK)
void bicycle_kernel(const __grid_constant__ CUtensorMap ta,   // acc  [B,256]
                    const __grid_constant__ CUtensorMap ts,   // steer[B,256]
                    const __grid_constant__ CUtensorMap to,   // out  [4,B,256]
                    const float* __restrict__ sx,
                    const float* __restrict__ sy,
                    const float* __restrict__ syaw,
                    const float* __restrict__ ssp)
{
    // Pool (28KB): cA[3][128] | cS[3][128] | sT[2][4][128]
    // every sub-buffer at a 2KB multiple -> uniform SW64 phase.
    __shared__ alignas(1024) float4 pool[1792];
    __shared__ alignas(8) unsigned long long mb[3];

    float4* cA = pool;                 // [3][128] accel tiles
    float4* cS = pool + 3 * CT4;       // [3][128] steer tiles
    float4* sT = pool + 6 * CT4;       // [2][4][128] state planes

    const int lane = threadIdx.x;
    const int vb0  = blockIdx.x * 64;            // job 0 base; job 1 = vb0+32
    const int b0   = vb0 + lane;

    // Preload BOTH jobs' initial states.
    float x  = sx[b0],      y  = sy[b0];
    float yaw = syaw[b0],   sp = ssp[b0];
    const float x1 = sx[b0 + 32],   y1 = sy[b0 + 32];
    const float w1 = syaw[b0 + 32], s1 = ssp[b0 + 32];

    const uint32_t mb0u = s2u(&mb[0]);
    const uint32_t cAu  = s2u(cA);
    const uint32_t cSu  = s2u(cS);
    const uint32_t sTu  = s2u(sT);

    // SW64 swizzle: f4 column = q ^ (((base>>7) + (v>>1)) & 3).
    const int sw = (int)(((cAu >> 7) + (lane >> 1)) & 3);

    if (lane == 0) {
        asm volatile("mbarrier.init.shared.b64 [%0], 1;" :: "r"(mb0u)      : "memory");
        asm volatile("mbarrier.init.shared.b64 [%0], 1;" :: "r"(mb0u + 8)  : "memory");
        asm volatile("mbarrier.init.shared.b64 [%0], 1;" :: "r"(mb0u + 16) : "memory");
        asm volatile("fence.proxy.async.shared::cta;" ::: "memory");
    }
    __syncwarp();

    // chunk g: job = g>>4, tcoord = (g&15)*16, vcoord = vb0 + (g>>4)*32,
    // ctrl buffer = g%3, mbar phase = (g/3)&1.
#define ISSUE_LOAD(gg, bb) do {                                               \
        uint32_t mbar = mb0u + (bb) * 8;                                      \
        uint32_t da = cAu + (bb) * (CT4 * 16);                                \
        uint32_t ds = cSu + (bb) * (CT4 * 16);                                \
        int vcoord = vb0 + (((gg) >> 4) << 5);                                \
        int tcoord = ((gg) & 15) * 16;                                        \
        asm volatile("mbarrier.arrive.expect_tx.shared.b64 _, [%0], %1;"      \
                     :: "r"(mbar), "r"(4096u) : "memory");                    \
        asm volatile("cp.async.bulk.tensor.2d.shared::cta.global.tile"        \
                     ".mbarrier::complete_tx::bytes [%0], [%1, {%2, %3}], [%4];" \
                     :: "r"(da), "l"(&ta), "r"(tcoord), "r"(vcoord), "r"(mbar) \
                     : "memory");                                             \
        asm volatile("cp.async.bulk.tensor.2d.shared::cta.global.tile"        \
                     ".mbarrier::complete_tx::bytes [%0], [%1, {%2, %3}], [%4];" \
                     :: "r"(ds), "l"(&ts), "r"(tcoord), "r"(vcoord), "r"(mbar) \
                     : "memory");                                             \
    } while (0)

    if (lane == 0) { ISSUE_LOAD(0, 0); ISSUE_LOAD(1, 1); }

#define STEP(A, ST) do {                                                     \
        float fr   = fmaf(0.01f * sp, sp, 0.1f * sp);                        \
        float spn  = fminf(fmaxf(fmaf(DT, (A) - fr, sp), 0.0f), MAX_SPEED);  \
        float sc   = fminf(fmaxf((ST), -MAX_STEER), MAX_STEER);              \
        float angv = sp * __tanf(sc) * INV_WB;                               \
        float sn, cc2;                                                       \
        __sincosf(yaw, &sn, &cc2);                                           \
        x   = fmaf(sp * cc2, DT, x);                                         \
        y   = fmaf(sp * sn, DT, y);                                          \
        yaw = fmaf(angv, DT, yaw);                                           \
        sp  = spn;                                                           \
    } while (0)

    for (int g = 0; g < NCH; ++g) {
        const int cbuf = g % 3;
        const int cph  = (g / 3) & 1;

        // Job switch: reset state registers for the second vehicle group.
        if (g == 16) { x = x1; y = y1; yaw = w1; sp = s1; }

        // Prefetch chunk g+2 NOW: its buffer ((g+2)%3 == (g-1)%3) went idle
        // when chunk g-1 finished; issuing before this chunk's waits keeps
        // 2 chunks of loads continuously in flight.
        if (lane == 0 && g + 2 < NCH) {
            const int nb = (g + 2) % 3;
            ISSUE_LOAD(g + 2, nb);
        }

        // Wait for this chunk's control tiles (acquire).
        {
            uint32_t mbar = mb0u + cbuf * 8;
            uint32_t done;
            asm volatile("{\n\t.reg .pred p;\n\t"
                         "mbarrier.try_wait.parity.acquire.cta.shared::cta.b64 p, [%1], %2;\n\t"
                         "selp.b32 %0, 1, 0, p;\n\t}"
                         : "=r"(done) : "r"(mbar), "r"(cph) : "memory");
            if (!done) {
                asm volatile("{\n\t.reg .pred P1;\n\t"
                             "W%=:\n\t"
                             "mbarrier.try_wait.parity.acquire.cta.shared::cta.b64 P1, [%0], %1, 0x989680;\n\t"
                             "@P1 bra.uni D%=;\n\t"
                             "bra.uni W%=;\n\t"
                             "D%=:\n\t}"
                             :: "r"(mbar), "r"(cph) : "memory");
            }
        }

        // State buffer reuse: chunk g-2's TMA store (same buffer) must be
        // done reading smem; tolerate one outstanding group -> overlap.
        if (g >= 2) {
            if (lane == 0)
                asm volatile("cp.async.bulk.wait_group.read 1;" ::: "memory");
            __syncwarp();
        }

        const float4* A4p = cA + cbuf * CT4;
        const float4* S4p = cS + cbuf * CT4;
        float4* P = sT + (g & 1) * (4 * CT4);

#pragma unroll
        for (int q = 0; q < 4; ++q) {
            const int si = lane * 4 + (q ^ sw);
            float4 A4 = A4p[si];
            float4 S4 = S4p[si];
            float4 X, Y, W, S;
            X.x = x; Y.x = y; W.x = yaw; S.x = sp;  STEP(A4.x, S4.x);
            X.y = x; Y.y = y; W.y = yaw; S.y = sp;  STEP(A4.y, S4.y);
            X.z = x; Y.z = y; W.z = yaw; S.z = sp;  STEP(A4.z, S4.z);
            X.w = x; Y.w = y; W.w = yaw; S.w = sp;  STEP(A4.w, S4.w);
            P[si]       = X;            // plane 0: x
            P[128 + si] = Y;            // plane 1: y
            P[256 + si] = W;            // plane 2: yaw
            P[384 + si] = S;            // plane 3: speed
        }
        __syncwarp();

        // One 3D TMA store covers all 4 planes.
        if (lane == 0) {
            asm volatile("fence.proxy.async.shared::cta;" ::: "memory");
            uint32_t src = sTu + (g & 1) * (4 * CT4 * 16);
            int vcoord = vb0 + ((g >> 4) << 5);
            int tcoord = (g & 15) * 16;
            asm volatile("cp.async.bulk.tensor.3d.global.shared::cta.tile.bulk_group"
                         " [%0, {%1, %2, %3}], [%4];"
                         :: "l"(&to), "r"(tcoord), "r"(vcoord), "r"(0), "r"(src)
                         : "memory");
            asm volatile("cp.async.bulk.commit_group;" ::: "memory");
        }
        __syncwarp();
    }

    if (lane == 0)
        asm volatile("cp.async.bulk.wait_group 0;" ::: "memory");
#undef STEP
#undef ISSUE_LOAD
}

// ---------------- host ----------------

typedef CUresult (*EncodeFn)(CUtensorMap*, CUtensorMapDataType, cuuint32_t, void*,
                             const cuuint64_t*, const cuuint64_t*,
                             const cuuint32_t*, const cuuint32_t*,
                             CUtensorMapInterleave, CUtensorMapSwizzle,
                             CUtensorMapL2promotion, CUtensorMapFloatOOBfill);

extern "C" void kernel_launch(void* const* d_in, const int* in_sizes, int n_in,
                              void* d_out, int out_size)
{
    (void)in_sizes; (void)n_in; (void)out_size;

    void* fptr = nullptr;
    cudaDriverEntryPointQueryResult qr;
    cudaGetDriverEntryPointByVersion("cuTensorMapEncodeTiled", &fptr, 12000,
                                     cudaEnableDefault, &qr);
    EncodeFn encode = (EncodeFn)fptr;

    CUtensorMap ta, ts, to;

    // controls: [B, 256] f32, tile 16x32, SW64 (64B rows), L2 promote 256B
    {
        cuuint64_t dims[2]    = {NS, BV};
        cuuint64_t strides[1] = {NS * 4};
        cuuint32_t box[2]     = {16, 32};
        cuuint32_t es[2]      = {1, 1};
        encode(&ta, CU_TENSOR_MAP_DATA_TYPE_FLOAT32, 2, d_in[4], dims, strides,
               box, es, CU_TENSOR_MAP_INTERLEAVE_NONE, CU_TENSOR_MAP_SWIZZLE_64B,
               CU_TENSOR_MAP_L2_PROMOTION_L2_256B, CU_TENSOR_MAP_FLOAT_OOB_FILL_NONE);
        encode(&ts, CU_TENSOR_MAP_DATA_TYPE_FLOAT32, 2, d_in[5], dims, strides,
               box, es, CU_TENSOR_MAP_INTERLEAVE_NONE, CU_TENSOR_MAP_SWIZZLE_64B,
               CU_TENSOR_MAP_L2_PROMOTION_L2_256B, CU_TENSOR_MAP_FLOAT_OOB_FILL_NONE);
    }
    // output: [4, B, 256] f32, tile 16x32x4, SW64, L2 promote 256B
    {
        cuuint64_t dims[3]    = {NS, BV, 4};
        cuuint64_t strides[2] = {NS * 4, (cuuint64_t)BV * NS * 4};
        cuuint32_t box[3]     = {16, 32, 4};
        cuuint32_t es[3]      = {1, 1, 1};
        encode(&to, CU_TENSOR_MAP_DATA_TYPE_FLOAT32, 3, d_out, dims, strides,
               box, es, CU_TENSOR_MAP_INTERLEAVE_NONE, CU_TENSOR_MAP_SWIZZLE_64B,
               CU_TENSOR_MAP_L2_PROMOTION_L2_256B, CU_TENSOR_MAP_FLOAT_OOB_FILL_NONE);
    }

    bicycle_kernel<<<BV / 64, BLK>>>(
        ta, ts, to,
        (const float*)d_in[0], (const float*)d_in[1],
        (const float*)d_in[2], (const float*)d_in[3]);
}